// round 3
// baseline (speedup 1.0000x reference)
#include <cuda_runtime.h>
#include <cuda_bf16.h>

// Problem constants
#define BATCH   512
#define NACT    256
#define ENT_D   256
#define REL_D   256
#define HIST_D  512
#define ACT_DIM 512           // ENT_D + REL_D
#define IN_DIM  1024          // ENT_D + HIST_D + REL_D
#define HUGE_F  1e31f
#define EPS_F   1e-20f

// Scratch (no cudaMalloc allowed). Referenced ONLY inside device code.
__device__ float g_X [BATCH * IN_DIM];    // [512,1024] concat input
__device__ float g_H [BATCH * ACT_DIM];   // relu(X@W1+b1)
__device__ float g_X2[BATCH * ACT_DIM];   // H@W2+b2

// ---------------------------------------------------------------------------
// Kernel 1: build X = [ent_emb[cur] | hist | rel_emb[qr]]   (float4 copies)
// ---------------------------------------------------------------------------
__global__ void build_x_kernel(const int* __restrict__ cur,
                               const int* __restrict__ qr,
                               const float* __restrict__ hist,
                               const float* __restrict__ ent_emb,
                               const float* __restrict__ rel_emb) {
    int b = blockIdx.x;
    int t = threadIdx.x;                       // 0..255, one float4 each
    const float4* ep = reinterpret_cast<const float4*>(ent_emb + (size_t)cur[b] * ENT_D);
    const float4* rp = reinterpret_cast<const float4*>(rel_emb + (size_t)qr[b]  * REL_D);
    const float4* hp = reinterpret_cast<const float4*>(hist + (size_t)b * HIST_D);
    float4* xrow = reinterpret_cast<float4*>(g_X + (size_t)b * IN_DIM);
    float4 v;
    if (t < 64)        v = ep[t];              // 256 floats
    else if (t < 192)  v = hp[t - 64];         // 512 floats
    else               v = rp[t - 192];        // 256 floats
    xrow[t] = v;
}

// ---------------------------------------------------------------------------
// Kernel 2/3: tiled fp32 GEMM  C[M,N] = act(A[M,K] @ W[K,N] + bias)
// BM=32, BN=64, BK=16, 256 threads, 2x4 micro-tile. 128 blocks -> ~0.87 waves.
// FIRST=true : A=g_X (K=1024), C=g_H, relu.  FIRST=false: A=g_H (K=512), C=g_X2.
// ---------------------------------------------------------------------------
template <int K, bool FIRST>
__global__ void gemm_kernel(const float* __restrict__ W,
                            const float* __restrict__ bias) {
    const float* A = FIRST ? (const float*)g_X : (const float*)g_H;
    float*       C = FIRST ? (float*)g_H : (float*)g_X2;
    const int N = ACT_DIM;

    __shared__ float As[16][32];   // As[kk][row]
    __shared__ float Bs[16][64];   // Bs[kk][col]

    int tid  = threadIdx.x;                 // 0..255
    int brow = blockIdx.y * 32;
    int bcol = blockIdx.x * 64;
    int tr   = (tid / 16) * 2;              // 0..30
    int tc   = (tid % 16) * 4;              // 0..60

    float acc[2][4];
#pragma unroll
    for (int i = 0; i < 2; i++)
#pragma unroll
        for (int j = 0; j < 4; j++) acc[i][j] = 0.f;

    for (int k0 = 0; k0 < K; k0 += 16) {
        // A tile: 32x16 = 512 elems, 2 per thread
#pragma unroll
        for (int r = 0; r < 2; r++) {
            int idx = tid + r * 256;
            int row = idx >> 4;             // 0..31
            int kk  = idx & 15;
            As[kk][row] = A[(size_t)(brow + row) * K + k0 + kk];
        }
        // B tile: 16x64 = 1024 elems, 4 per thread (coalesced)
#pragma unroll
        for (int r = 0; r < 4; r++) {
            int idx = tid + r * 256;
            int kk  = idx >> 6;             // 0..15
            int col = idx & 63;
            Bs[kk][col] = W[(size_t)(k0 + kk) * N + bcol + col];
        }
        __syncthreads();

#pragma unroll
        for (int kk = 0; kk < 16; kk++) {
            float ra0 = As[kk][tr];
            float ra1 = As[kk][tr + 1];
            float rb[4];
#pragma unroll
            for (int j = 0; j < 4; j++) rb[j] = Bs[kk][tc + j];
#pragma unroll
            for (int j = 0; j < 4; j++) {
                acc[0][j] += ra0 * rb[j];
                acc[1][j] += ra1 * rb[j];
            }
        }
        __syncthreads();
    }

#pragma unroll
    for (int i = 0; i < 2; i++) {
#pragma unroll
        for (int j = 0; j < 4; j++) {
            float v = acc[i][j] + bias[bcol + tc + j];
            if (FIRST) v = fmaxf(v, 0.f);
            C[(size_t)(brow + tr + i) * N + bcol + tc + j] = v;
        }
    }
}

// ---------------------------------------------------------------------------
// Kernel 4: scores (gather-dot) + masked softmax + entropy.
// One block per batch row, 256 threads (8 warps). Warp-per-action dots with
// float4 coalesced loads. out: [0..B*A) action_dist, [B*A..B*A+B) entropy.
// ---------------------------------------------------------------------------
__global__ void score_softmax_kernel(const int* __restrict__ r_space,
                                     const int* __restrict__ e_space,
                                     const int* __restrict__ amask,
                                     const float* __restrict__ rel_emb,
                                     const float* __restrict__ ent_emb,
                                     float* __restrict__ out) {
    int b    = blockIdx.x;
    int tid  = threadIdx.x;
    int lane = tid & 31;
    int warp = tid >> 5;

    __shared__ float x2s[ACT_DIM];
    __shared__ float sc[NACT];
    __shared__ float red[8];

    // stage X2[b]
    x2s[tid]       = g_X2[(size_t)b * ACT_DIM + tid];
    x2s[tid + 256] = g_X2[(size_t)b * ACT_DIM + tid + 256];
    __syncthreads();

    const float4* xa = reinterpret_cast<const float4*>(x2s);        // 128 float4

    // warp-per-action: warp w handles a = w, w+8, ...
    for (int a = warp; a < NACT; a += 8) {
        int r = r_space[b * NACT + a];
        int e = e_space[b * NACT + a];
        const float4* rp4 = reinterpret_cast<const float4*>(rel_emb + (size_t)r * REL_D);
        const float4* ep4 = reinterpret_cast<const float4*>(ent_emb + (size_t)e * ENT_D);
        float s = 0.f;
#pragma unroll
        for (int i = 0; i < 2; i++) {
            int k = lane + i * 32;          // 64 float4 = 256 floats
            float4 rv = rp4[k], xv = xa[k];
            s += rv.x * xv.x + rv.y * xv.y + rv.z * xv.z + rv.w * xv.w;
            float4 ev = ep4[k], xw = xa[64 + k];
            s += ev.x * xw.x + ev.y * xw.y + ev.z * xw.z + ev.w * xw.w;
        }
#pragma unroll
        for (int o = 16; o; o >>= 1) s += __shfl_xor_sync(0xffffffffu, s, o);
        if (lane == 0) {
            float m = (float)amask[b * NACT + a];
            sc[a] = s - (1.0f - m) * HUGE_F;
        }
    }
    __syncthreads();

    float v = sc[tid];

    // block max
    float m = v;
#pragma unroll
    for (int o = 16; o; o >>= 1) m = fmaxf(m, __shfl_xor_sync(0xffffffffu, m, o));
    if (lane == 0) red[warp] = m;
    __syncthreads();
    float mx = red[0];
#pragma unroll
    for (int i = 1; i < 8; i++) mx = fmaxf(mx, red[i]);
    __syncthreads();

    // sum of exp
    float ev = expf(v - mx);
    float s = ev;
#pragma unroll
    for (int o = 16; o; o >>= 1) s += __shfl_xor_sync(0xffffffffu, s, o);
    if (lane == 0) red[warp] = s;
    __syncthreads();
    float tot = red[0];
#pragma unroll
    for (int i = 1; i < 8; i++) tot += red[i];
    __syncthreads();

    float p = ev / tot;
    out[(size_t)b * NACT + tid] = p;

    // entropy = -sum p*log(p+eps)
    float et = -p * logf(p + EPS_F);
#pragma unroll
    for (int o = 16; o; o >>= 1) et += __shfl_xor_sync(0xffffffffu, et, o);
    if (lane == 0) red[warp] = et;
    __syncthreads();
    if (tid == 0) {
        float e = red[0];
#pragma unroll
        for (int i = 1; i < 8; i++) e += red[i];
        out[(size_t)BATCH * NACT + b] = e;
    }
}

// ---------------------------------------------------------------------------
extern "C" void kernel_launch(void* const* d_in, const int* in_sizes, int n_in,
                              void* d_out, int out_size) {
    const int*   cur     = (const int*)  d_in[0];   // current_entity [B]
    const int*   qr      = (const int*)  d_in[1];   // query_relation [B]
    const float* hist    = (const float*)d_in[2];   // encoded_history [B,512]
    const int*   r_space = (const int*)  d_in[3];   // [B,A]
    const int*   e_space = (const int*)  d_in[4];   // [B,A]
    const int*   amask   = (const int*)  d_in[5];   // [B,A]
    const float* ent_emb = (const float*)d_in[6];   // [NUM_ENT,256]
    const float* rel_emb = (const float*)d_in[7];   // [NUM_REL,256]
    const float* W1      = (const float*)d_in[8];   // [1024,512]
    const float* b1      = (const float*)d_in[9];   // [512]
    const float* W2      = (const float*)d_in[10];  // [512,512]
    const float* b2      = (const float*)d_in[11];  // [512]
    float* out = (float*)d_out;

    build_x_kernel<<<BATCH, 256>>>(cur, qr, hist, ent_emb, rel_emb);

    dim3 grid(ACT_DIM / 64, BATCH / 32);   // 8 x 16 = 128 blocks
    gemm_kernel<IN_DIM,  true ><<<grid, 256>>>(W1, b1);
    gemm_kernel<ACT_DIM, false><<<grid, 256>>>(W2, b2);

    score_softmax_kernel<<<BATCH, 256>>>(r_space, e_space, amask,
                                         rel_emb, ent_emb, out);
}

// round 5
// speedup vs baseline: 1.2042x; 1.2042x over previous
#include <cuda_runtime.h>
#include <cuda_bf16.h>
#include <cstdint>

#define BATCH   512
#define NACT    256
#define ENT_D   256
#define REL_D   256
#define HIST_D  512
#define ACT_DIM 512
#define IN_DIM  1024
#define HUGE_F  1e31f
#define EPS_F   1e-20f

// Scratch (referenced only inside device code)
__device__ float g_X [BATCH * IN_DIM];
__device__ float g_H [BATCH * ACT_DIM];
__device__ float g_X2[BATCH * ACT_DIM];
__device__ float g_SC[BATCH * NACT];

__device__ __forceinline__ float to_tf32(float x) {
    uint32_t u;
    asm("cvt.rna.tf32.f32 %0, %1;" : "=r"(u) : "f"(x));
    return __uint_as_float(u);
}

// ---------------------------------------------------------------------------
// Kernel 1: X = [ent_emb[cur] | hist | rel_emb[qr]]  (float4)
// ---------------------------------------------------------------------------
__global__ void build_x_kernel(const int* __restrict__ cur,
                               const int* __restrict__ qr,
                               const float* __restrict__ hist,
                               const float* __restrict__ ent_emb,
                               const float* __restrict__ rel_emb) {
    int b = blockIdx.x;
    int t = threadIdx.x;  // 0..255
    const float4* ep = reinterpret_cast<const float4*>(ent_emb + (size_t)cur[b] * ENT_D);
    const float4* rp = reinterpret_cast<const float4*>(rel_emb + (size_t)qr[b]  * REL_D);
    const float4* hp = reinterpret_cast<const float4*>(hist + (size_t)b * HIST_D);
    float4* xrow = reinterpret_cast<float4*>(g_X + (size_t)b * IN_DIM);
    float4 v;
    if (t < 64)        v = ep[t];
    else if (t < 192)  v = hp[t - 64];
    else               v = rp[t - 192];
    xrow[t] = v;
}

// ---------------------------------------------------------------------------
// Kernel 2/3: tf32 tensor-core GEMM  C = act(A @ W + bias)
// 128 thr (4 warps), block tile 32x64, warp tile 16x32 (1x4 m16n8k8), BK=16.
// Grid (N/64=8, M/32=16) = 128 blocks.
// ---------------------------------------------------------------------------
template <int K, bool FIRST>
__global__ void mma_gemm_kernel(const float* __restrict__ W,
                                const float* __restrict__ bias) {
    const float* A = FIRST ? (const float*)g_X : (const float*)g_H;
    float*       C = FIRST ? (float*)g_H : (float*)g_X2;
    const int N = ACT_DIM;

    __shared__ float As[32][20];   // [row][k], pad 20 -> conflict-free frag loads
    __shared__ float Bs[16][64];   // [k][n]

    int tid   = threadIdx.x;
    int warp  = tid >> 5;          // 0..3
    int lane  = tid & 31;
    int group = lane >> 2;         // 0..7
    int tig   = lane & 3;          // 0..3

    int brow   = blockIdx.y * 32;
    int bcol   = blockIdx.x * 64;
    int warp_m = (warp >> 1) * 16;
    int warp_n = (warp & 1)  * 32;

    float c[4][4];
#pragma unroll
    for (int j = 0; j < 4; j++)
#pragma unroll
        for (int i = 0; i < 4; i++) c[j][i] = 0.f;

    int ar = tid >> 2;       // 0..31  A row
    int ac = tid & 3;        // float4 idx in k
    for (int k0 = 0; k0 < K; k0 += 16) {
        // A tile 32x16 (128 float4, 1 per thread)
        float4 av = *reinterpret_cast<const float4*>(&A[(size_t)(brow + ar) * K + k0 + ac * 4]);
        As[ar][ac * 4 + 0] = to_tf32(av.x);
        As[ar][ac * 4 + 1] = to_tf32(av.y);
        As[ar][ac * 4 + 2] = to_tf32(av.z);
        As[ar][ac * 4 + 3] = to_tf32(av.w);
        // B tile 16x64 (256 float4, 2 per thread)
#pragma unroll
        for (int it = 0; it < 2; it++) {
            int fid = tid + it * 128;
            int kk  = fid >> 4;
            int c4  = fid & 15;
            float4 bv = *reinterpret_cast<const float4*>(&W[(size_t)(k0 + kk) * N + bcol + c4 * 4]);
            Bs[kk][c4 * 4 + 0] = to_tf32(bv.x);
            Bs[kk][c4 * 4 + 1] = to_tf32(bv.y);
            Bs[kk][c4 * 4 + 2] = to_tf32(bv.z);
            Bs[kk][c4 * 4 + 3] = to_tf32(bv.w);
        }
        __syncthreads();

#pragma unroll
        for (int ks = 0; ks < 2; ks++) {
            int kb = ks * 8;
            uint32_t a0 = __float_as_uint(As[warp_m + group    ][kb + tig    ]);
            uint32_t a1 = __float_as_uint(As[warp_m + group + 8][kb + tig    ]);
            uint32_t a2 = __float_as_uint(As[warp_m + group    ][kb + tig + 4]);
            uint32_t a3 = __float_as_uint(As[warp_m + group + 8][kb + tig + 4]);
#pragma unroll
            for (int j = 0; j < 4; j++) {
                int col = warp_n + j * 8 + group;
                uint32_t b0 = __float_as_uint(Bs[kb + tig    ][col]);
                uint32_t b1 = __float_as_uint(Bs[kb + tig + 4][col]);
                asm volatile(
                    "mma.sync.aligned.m16n8k8.row.col.f32.tf32.tf32.f32 "
                    "{%0,%1,%2,%3}, {%4,%5,%6,%7}, {%8,%9}, {%0,%1,%2,%3};"
                    : "+f"(c[j][0]), "+f"(c[j][1]), "+f"(c[j][2]), "+f"(c[j][3])
                    : "r"(a0), "r"(a1), "r"(a2), "r"(a3), "r"(b0), "r"(b1));
            }
        }
        __syncthreads();
    }

    // epilogue
#pragma unroll
    for (int j = 0; j < 4; j++) {
        int row = brow + warp_m + group;
        int col = bcol + warp_n + j * 8 + 2 * tig;
        float bc0 = bias[col], bc1 = bias[col + 1];
        float v00 = c[j][0] + bc0, v01 = c[j][1] + bc1;
        float v10 = c[j][2] + bc0, v11 = c[j][3] + bc1;
        if (FIRST) {
            v00 = fmaxf(v00, 0.f); v01 = fmaxf(v01, 0.f);
            v10 = fmaxf(v10, 0.f); v11 = fmaxf(v11, 0.f);
        }
        C[(size_t)row * N + col]           = v00;
        C[(size_t)row * N + col + 1]       = v01;
        C[(size_t)(row + 8) * N + col]     = v10;
        C[(size_t)(row + 8) * N + col + 1] = v11;
    }
}

// ---------------------------------------------------------------------------
// Kernel 4: masked scores (gather + dot). grid (4, B), 256 thr.
// Block (q,b) handles actions [q*64, q*64+64); 8 warps x 8 actions.
// ---------------------------------------------------------------------------
__global__ void scores_kernel(const int* __restrict__ r_space,
                              const int* __restrict__ e_space,
                              const int* __restrict__ amask,
                              const float* __restrict__ rel_emb,
                              const float* __restrict__ ent_emb) {
    int b    = blockIdx.y;
    int abase= blockIdx.x * 64;
    int tid  = threadIdx.x;
    int lane = tid & 31;
    int warp = tid >> 5;

    __shared__ float x2s[ACT_DIM];
    x2s[tid]       = g_X2[(size_t)b * ACT_DIM + tid];
    x2s[tid + 256] = g_X2[(size_t)b * ACT_DIM + tid + 256];
    __syncthreads();

    const float4* xa = reinterpret_cast<const float4*>(x2s);

#pragma unroll
    for (int i = 0; i < 8; i++) {
        int a = abase + warp + i * 8;
        int r = r_space[b * NACT + a];
        int e = e_space[b * NACT + a];
        const float4* rp4 = reinterpret_cast<const float4*>(rel_emb + (size_t)r * REL_D);
        const float4* ep4 = reinterpret_cast<const float4*>(ent_emb + (size_t)e * ENT_D);
        float s = 0.f;
#pragma unroll
        for (int k4 = 0; k4 < 2; k4++) {
            int k = lane + k4 * 32;
            float4 rv = rp4[k], xv = xa[k];
            s += rv.x * xv.x + rv.y * xv.y + rv.z * xv.z + rv.w * xv.w;
            float4 ev = ep4[k], xw = xa[64 + k];
            s += ev.x * xw.x + ev.y * xw.y + ev.z * xw.z + ev.w * xw.w;
        }
#pragma unroll
        for (int o = 16; o; o >>= 1) s += __shfl_xor_sync(0xffffffffu, s, o);
        if (lane == 0) {
            float m = (float)amask[b * NACT + a];
            g_SC[b * NACT + a] = s - (1.0f - m) * HUGE_F;
        }
    }
}

// ---------------------------------------------------------------------------
// Kernel 5: softmax + entropy per row. 512 blocks x 256 thr.
// ---------------------------------------------------------------------------
__global__ void softmax_kernel(float* __restrict__ out) {
    int b    = blockIdx.x;
    int tid  = threadIdx.x;
    int lane = tid & 31;
    int warp = tid >> 5;
    __shared__ float red[8];

    float v = g_SC[b * NACT + tid];

    float m = v;
#pragma unroll
    for (int o = 16; o; o >>= 1) m = fmaxf(m, __shfl_xor_sync(0xffffffffu, m, o));
    if (lane == 0) red[warp] = m;
    __syncthreads();
    float mx = red[0];
#pragma unroll
    for (int i = 1; i < 8; i++) mx = fmaxf(mx, red[i]);
    __syncthreads();

    float ev = expf(v - mx);
    float s = ev;
#pragma unroll
    for (int o = 16; o; o >>= 1) s += __shfl_xor_sync(0xffffffffu, s, o);
    if (lane == 0) red[warp] = s;
    __syncthreads();
    float tot = red[0];
#pragma unroll
    for (int i = 1; i < 8; i++) tot += red[i];
    __syncthreads();

    float p = ev / tot;
    out[(size_t)b * NACT + tid] = p;

    float et = -p * logf(p + EPS_F);
#pragma unroll
    for (int o = 16; o; o >>= 1) et += __shfl_xor_sync(0xffffffffu, et, o);
    if (lane == 0) red[warp] = et;
    __syncthreads();
    if (tid == 0) {
        float e = red[0];
#pragma unroll
        for (int i = 1; i < 8; i++) e += red[i];
        out[(size_t)BATCH * NACT + b] = e;
    }
}

// ---------------------------------------------------------------------------
extern "C" void kernel_launch(void* const* d_in, const int* in_sizes, int n_in,
                              void* d_out, int out_size) {
    const int*   cur     = (const int*)  d_in[0];
    const int*   qr      = (const int*)  d_in[1];
    const float* hist    = (const float*)d_in[2];
    const int*   r_space = (const int*)  d_in[3];
    const int*   e_space = (const int*)  d_in[4];
    const int*   amask   = (const int*)  d_in[5];
    const float* ent_emb = (const float*)d_in[6];
    const float* rel_emb = (const float*)d_in[7];
    const float* W1      = (const float*)d_in[8];
    const float* b1      = (const float*)d_in[9];
    const float* W2      = (const float*)d_in[10];
    const float* b2      = (const float*)d_in[11];
    float* out = (float*)d_out;

    build_x_kernel<<<BATCH, 256>>>(cur, qr, hist, ent_emb, rel_emb);

    dim3 ggrid(ACT_DIM / 64, BATCH / 32);    // 8 x 16 = 128 blocks
    mma_gemm_kernel<IN_DIM,  true ><<<ggrid, 128>>>(W1, b1);
    mma_gemm_kernel<ACT_DIM, false><<<ggrid, 128>>>(W2, b2);

    dim3 sgrid(4, BATCH);
    scores_kernel<<<sgrid, 256>>>(r_space, e_space, amask, rel_emb, ent_emb);

    softmax_kernel<<<BATCH, 256>>>(out);
}

// round 6
// speedup vs baseline: 1.4992x; 1.2449x over previous
#include <cuda_runtime.h>
#include <cuda_bf16.h>
#include <cstdint>

#define BATCH   512
#define NACT    256
#define ENT_D   256
#define REL_D   256
#define HIST_D  512
#define ACT_DIM 512
#define IN_DIM  1024
#define HUGE_F  1e31f
#define EPS_F   1e-20f

// Scratch (referenced only inside device code)
__device__ float g_X [BATCH * IN_DIM];
__device__ float g_H [BATCH * ACT_DIM];
__device__ float g_X2[BATCH * ACT_DIM];
__device__ float g_SC[BATCH * NACT];

__device__ __forceinline__ float to_tf32(float x) {
    uint32_t u;
    asm("cvt.rna.tf32.f32 %0, %1;" : "=r"(u) : "f"(x));
    return __uint_as_float(u);
}

// ---------------------------------------------------------------------------
// Kernel 1: X = [ent_emb[cur] | hist | rel_emb[qr]]  (float4)
// ---------------------------------------------------------------------------
__global__ void build_x_kernel(const int* __restrict__ cur,
                               const int* __restrict__ qr,
                               const float* __restrict__ hist,
                               const float* __restrict__ ent_emb,
                               const float* __restrict__ rel_emb) {
    int b = blockIdx.x;
    int t = threadIdx.x;  // 0..255
    const float4* ep = reinterpret_cast<const float4*>(ent_emb + (size_t)cur[b] * ENT_D);
    const float4* rp = reinterpret_cast<const float4*>(rel_emb + (size_t)qr[b]  * REL_D);
    const float4* hp = reinterpret_cast<const float4*>(hist + (size_t)b * HIST_D);
    float4* xrow = reinterpret_cast<float4*>(g_X + (size_t)b * IN_DIM);
    float4 v;
    if (t < 64)        v = ep[t];
    else if (t < 192)  v = hp[t - 64];
    else               v = rp[t - 192];
    xrow[t] = v;
}

// ---------------------------------------------------------------------------
// Kernel 2/3: tf32 tensor-core GEMM  C = act(A @ W + bias)
// 256 thr (8 warps), block tile 32x64, warp tile 16x16, BK=32.
// Grid (8, 16) = 128 blocks. Conflict-free smem strides (36 / 72).
// ---------------------------------------------------------------------------
template <int K, bool FIRST>
__global__ void mma_gemm_kernel(const float* __restrict__ W,
                                const float* __restrict__ bias) {
    const float* A = FIRST ? (const float*)g_X : (const float*)g_H;
    float*       C = FIRST ? (float*)g_H : (float*)g_X2;
    const int N = ACT_DIM;

    __shared__ float As[32][36];   // [row][k]   bank = 4*group+tig  (distinct)
    __shared__ float Bs[32][72];   // [k][n]     bank = 8*tig+group  (distinct)

    int tid   = threadIdx.x;
    int warp  = tid >> 5;          // 0..7
    int lane  = tid & 31;
    int group = lane >> 2;         // 0..7
    int tig   = lane & 3;          // 0..3

    int brow   = blockIdx.y * 32;
    int bcol   = blockIdx.x * 64;
    int warp_m = (warp >> 2) * 16; // 0 / 16
    int warp_n = (warp & 3)  * 16; // 0,16,32,48

    float c[2][4];
#pragma unroll
    for (int j = 0; j < 2; j++)
#pragma unroll
        for (int i = 0; i < 4; i++) c[j][i] = 0.f;

    int ar = tid >> 3;       // 0..31 (A row)
    int ac = tid & 7;        // 0..7  (float4 idx in k)
    for (int k0 = 0; k0 < K; k0 += 32) {
        // A tile 32x32 (256 float4, 1 per thread)
        float4 av = *reinterpret_cast<const float4*>(&A[(size_t)(brow + ar) * K + k0 + ac * 4]);
        As[ar][ac * 4 + 0] = to_tf32(av.x);
        As[ar][ac * 4 + 1] = to_tf32(av.y);
        As[ar][ac * 4 + 2] = to_tf32(av.z);
        As[ar][ac * 4 + 3] = to_tf32(av.w);
        // B tile 32x64 (512 float4, 2 per thread)
#pragma unroll
        for (int it = 0; it < 2; it++) {
            int fid = tid + it * 256;
            int kk  = fid >> 4;             // 0..31
            int c4  = fid & 15;
            float4 bv = *reinterpret_cast<const float4*>(&W[(size_t)(k0 + kk) * N + bcol + c4 * 4]);
            Bs[kk][c4 * 4 + 0] = to_tf32(bv.x);
            Bs[kk][c4 * 4 + 1] = to_tf32(bv.y);
            Bs[kk][c4 * 4 + 2] = to_tf32(bv.z);
            Bs[kk][c4 * 4 + 3] = to_tf32(bv.w);
        }
        __syncthreads();

#pragma unroll
        for (int ks = 0; ks < 4; ks++) {
            int kb = ks * 8;
            uint32_t a0 = __float_as_uint(As[warp_m + group    ][kb + tig    ]);
            uint32_t a1 = __float_as_uint(As[warp_m + group + 8][kb + tig    ]);
            uint32_t a2 = __float_as_uint(As[warp_m + group    ][kb + tig + 4]);
            uint32_t a3 = __float_as_uint(As[warp_m + group + 8][kb + tig + 4]);
#pragma unroll
            for (int j = 0; j < 2; j++) {
                int col = warp_n + j * 8 + group;
                uint32_t b0 = __float_as_uint(Bs[kb + tig    ][col]);
                uint32_t b1 = __float_as_uint(Bs[kb + tig + 4][col]);
                asm volatile(
                    "mma.sync.aligned.m16n8k8.row.col.f32.tf32.tf32.f32 "
                    "{%0,%1,%2,%3}, {%4,%5,%6,%7}, {%8,%9}, {%0,%1,%2,%3};"
                    : "+f"(c[j][0]), "+f"(c[j][1]), "+f"(c[j][2]), "+f"(c[j][3])
                    : "r"(a0), "r"(a1), "r"(a2), "r"(a3), "r"(b0), "r"(b1));
            }
        }
        __syncthreads();
    }

    // epilogue (m16n8 frag: rows group/group+8, cols 2*tig + {0,1} + j*8)
#pragma unroll
    for (int j = 0; j < 2; j++) {
        int row = brow + warp_m + group;
        int col = bcol + warp_n + j * 8 + 2 * tig;
        float bc0 = bias[col], bc1 = bias[col + 1];
        float v00 = c[j][0] + bc0, v01 = c[j][1] + bc1;
        float v10 = c[j][2] + bc0, v11 = c[j][3] + bc1;
        if (FIRST) {
            v00 = fmaxf(v00, 0.f); v01 = fmaxf(v01, 0.f);
            v10 = fmaxf(v10, 0.f); v11 = fmaxf(v11, 0.f);
        }
        C[(size_t)row * N + col]           = v00;
        C[(size_t)row * N + col + 1]       = v01;
        C[(size_t)(row + 8) * N + col]     = v10;
        C[(size_t)(row + 8) * N + col + 1] = v11;
    }
}

// ---------------------------------------------------------------------------
// Kernel 4: masked scores. 8 threads per action, 32 actions per block.
// grid (8, B) = 4096 blocks, 256 thr. 16 independent float4 LDGs per thread.
// ---------------------------------------------------------------------------
__global__ void scores_kernel(const int* __restrict__ r_space,
                              const int* __restrict__ e_space,
                              const int* __restrict__ amask,
                              const float* __restrict__ rel_emb,
                              const float* __restrict__ ent_emb) {
    int b     = blockIdx.y;
    int tid   = threadIdx.x;
    int al    = tid >> 3;            // action-local 0..31
    int sub   = tid & 7;             // lane within action group
    int a     = blockIdx.x * 32 + al;

    __shared__ float x2s[ACT_DIM];
    x2s[tid]       = g_X2[(size_t)b * ACT_DIM + tid];
    x2s[tid + 256] = g_X2[(size_t)b * ACT_DIM + tid + 256];
    __syncthreads();

    int r = r_space[b * NACT + a];
    int e = e_space[b * NACT + a];
    const float4* rp4 = reinterpret_cast<const float4*>(rel_emb + (size_t)r * REL_D);
    const float4* ep4 = reinterpret_cast<const float4*>(ent_emb + (size_t)e * ENT_D);
    const float4* xa  = reinterpret_cast<const float4*>(x2s);

    float s = 0.f;
#pragma unroll
    for (int i = 0; i < 8; i++) {
        int k = sub + i * 8;                          // 64 float4 over rel
        float4 rv = rp4[k], xv = xa[k];
        s += rv.x * xv.x + rv.y * xv.y + rv.z * xv.z + rv.w * xv.w;
    }
#pragma unroll
    for (int i = 0; i < 8; i++) {
        int k = sub + i * 8;                          // 64 float4 over ent
        float4 ev = ep4[k], xw = xa[64 + k];
        s += ev.x * xw.x + ev.y * xw.y + ev.z * xw.z + ev.w * xw.w;
    }
    // reduce across the 8-lane group (lane bits 0..2)
    s += __shfl_xor_sync(0xffffffffu, s, 1);
    s += __shfl_xor_sync(0xffffffffu, s, 2);
    s += __shfl_xor_sync(0xffffffffu, s, 4);

    if (sub == 0) {
        float m = (float)amask[b * NACT + a];
        g_SC[b * NACT + a] = s - (1.0f - m) * HUGE_F;
    }
}

// ---------------------------------------------------------------------------
// Kernel 5: softmax + entropy per row. 512 blocks x 256 thr.
// ---------------------------------------------------------------------------
__global__ void softmax_kernel(float* __restrict__ out) {
    int b    = blockIdx.x;
    int tid  = threadIdx.x;
    int lane = tid & 31;
    int warp = tid >> 5;
    __shared__ float red[8];

    float v = g_SC[b * NACT + tid];

    float m = v;
#pragma unroll
    for (int o = 16; o; o >>= 1) m = fmaxf(m, __shfl_xor_sync(0xffffffffu, m, o));
    if (lane == 0) red[warp] = m;
    __syncthreads();
    float mx = red[0];
#pragma unroll
    for (int i = 1; i < 8; i++) mx = fmaxf(mx, red[i]);
    __syncthreads();

    float ev = expf(v - mx);
    float s = ev;
#pragma unroll
    for (int o = 16; o; o >>= 1) s += __shfl_xor_sync(0xffffffffu, s, o);
    if (lane == 0) red[warp] = s;
    __syncthreads();
    float tot = red[0];
#pragma unroll
    for (int i = 1; i < 8; i++) tot += red[i];
    __syncthreads();

    float p = ev / tot;
    out[(size_t)b * NACT + tid] = p;

    float et = -p * logf(p + EPS_F);
#pragma unroll
    for (int o = 16; o; o >>= 1) et += __shfl_xor_sync(0xffffffffu, et, o);
    if (lane == 0) red[warp] = et;
    __syncthreads();
    if (tid == 0) {
        float e = red[0];
#pragma unroll
        for (int i = 1; i < 8; i++) e += red[i];
        out[(size_t)BATCH * NACT + b] = e;
    }
}

// ---------------------------------------------------------------------------
extern "C" void kernel_launch(void* const* d_in, const int* in_sizes, int n_in,
                              void* d_out, int out_size) {
    const int*   cur     = (const int*)  d_in[0];
    const int*   qr      = (const int*)  d_in[1];
    const float* hist    = (const float*)d_in[2];
    const int*   r_space = (const int*)  d_in[3];
    const int*   e_space = (const int*)  d_in[4];
    const int*   amask   = (const int*)  d_in[5];
    const float* ent_emb = (const float*)d_in[6];
    const float* rel_emb = (const float*)d_in[7];
    const float* W1      = (const float*)d_in[8];
    const float* b1      = (const float*)d_in[9];
    const float* W2      = (const float*)d_in[10];
    const float* b2      = (const float*)d_in[11];
    float* out = (float*)d_out;

    build_x_kernel<<<BATCH, 256>>>(cur, qr, hist, ent_emb, rel_emb);

    dim3 ggrid(ACT_DIM / 64, BATCH / 32);    // 8 x 16 = 128 blocks
    mma_gemm_kernel<IN_DIM,  true ><<<ggrid, 256>>>(W1, b1);
    mma_gemm_kernel<ACT_DIM, false><<<ggrid, 256>>>(W2, b2);

    dim3 sgrid(NACT / 32, BATCH);            // 8 x 512 = 4096 blocks
    scores_kernel<<<sgrid, 256>>>(r_space, e_space, amask, rel_emb, ent_emb);

    softmax_kernel<<<BATCH, 256>>>(out);
}

// round 7
// speedup vs baseline: 1.7291x; 1.1534x over previous
#include <cuda_runtime.h>
#include <cuda_bf16.h>
#include <cstdint>

#define BATCH   512
#define NACT    256
#define ENT_D   256
#define REL_D   256
#define HIST_D  512
#define ACT_DIM 512
#define IN_DIM  1024
#define HUGE_F  1e31f
#define EPS_F   1e-20f

// Scratch (referenced only inside device code)
__device__ float g_H [BATCH * ACT_DIM];
__device__ float g_X2[BATCH * ACT_DIM];
__device__ float g_SC[BATCH * NACT];

__device__ __forceinline__ float to_tf32(float x) {
    uint32_t u;
    asm("cvt.rna.tf32.f32 %0, %1;" : "=r"(u) : "f"(x));
    return __uint_as_float(u);
}

// ---------------------------------------------------------------------------
// GEMM: C = act(A @ W + bias), tf32 mma, double-buffered register prefetch.
// 256 thr (8 warps), block tile 32x64, warp tile 16x16, BK=32, grid 8x16.
// FIRST: A row is the virtual concat [ent_emb[cur]|hist|rel_emb[qr]] (K=1024).
// ---------------------------------------------------------------------------
template <int K, bool FIRST>
__global__ void mma_gemm_kernel(const float* __restrict__ W,
                                const float* __restrict__ bias,
                                const int* __restrict__ cur,
                                const int* __restrict__ qr,
                                const float* __restrict__ hist,
                                const float* __restrict__ ent_emb,
                                const float* __restrict__ rel_emb) {
    float* C = FIRST ? (float*)g_H : (float*)g_X2;
    const int N = ACT_DIM;

    __shared__ float As[2][32][36];   // [buf][row][k]
    __shared__ float Bs[2][32][72];   // [buf][k][n]

    int tid   = threadIdx.x;
    int warp  = tid >> 5;
    int lane  = tid & 31;
    int group = lane >> 2;            // 0..7
    int tig   = lane & 3;             // 0..3

    int brow   = blockIdx.y * 32;
    int bcol   = blockIdx.x * 64;
    int warp_m = (warp >> 2) * 16;
    int warp_n = (warp & 3)  * 16;

    // A-load geometry: one float4 per thread per tile
    int ar = tid >> 3;                // 0..31
    int ac = tid & 7;                 // 0..7 (float4 in k)
    int arow = brow + ar;
    int ce = 0, rr = 0;
    const float* Ah = nullptr;
    if (FIRST) { ce = cur[arow]; rr = qr[arow]; }
    else       { Ah = (const float*)g_H; }

    auto loadA = [&](int k0) -> float4 {
        int kk = k0 + ac * 4;
        if (FIRST) {
            if (kk < ENT_D)
                return *reinterpret_cast<const float4*>(ent_emb + (size_t)ce * ENT_D + kk);
            if (kk < ENT_D + HIST_D)
                return *reinterpret_cast<const float4*>(hist + (size_t)arow * HIST_D + (kk - ENT_D));
            return *reinterpret_cast<const float4*>(rel_emb + (size_t)rr * REL_D + (kk - ENT_D - HIST_D));
        } else {
            return *reinterpret_cast<const float4*>(Ah + (size_t)arow * ACT_DIM + kk);
        }
    };

    // B-load geometry: two float4 per thread per tile
    int bk0 = tid >> 4;               // 0..15
    int bc0 = tid & 15;
    auto loadB = [&](int k0, int it) -> float4 {
        int kk = bk0 + it * 16;
        return *reinterpret_cast<const float4*>(&W[(size_t)(k0 + kk) * N + bcol + bc0 * 4]);
    };
    auto storeTile = [&](int buf, float4 av, float4 bv0, float4 bv1) {
        As[buf][ar][ac * 4 + 0] = to_tf32(av.x);
        As[buf][ar][ac * 4 + 1] = to_tf32(av.y);
        As[buf][ar][ac * 4 + 2] = to_tf32(av.z);
        As[buf][ar][ac * 4 + 3] = to_tf32(av.w);
        Bs[buf][bk0     ][bc0 * 4 + 0] = to_tf32(bv0.x);
        Bs[buf][bk0     ][bc0 * 4 + 1] = to_tf32(bv0.y);
        Bs[buf][bk0     ][bc0 * 4 + 2] = to_tf32(bv0.z);
        Bs[buf][bk0     ][bc0 * 4 + 3] = to_tf32(bv0.w);
        Bs[buf][bk0 + 16][bc0 * 4 + 0] = to_tf32(bv1.x);
        Bs[buf][bk0 + 16][bc0 * 4 + 1] = to_tf32(bv1.y);
        Bs[buf][bk0 + 16][bc0 * 4 + 2] = to_tf32(bv1.z);
        Bs[buf][bk0 + 16][bc0 * 4 + 3] = to_tf32(bv1.w);
    };

    float c[2][4];
#pragma unroll
    for (int j = 0; j < 2; j++)
#pragma unroll
        for (int i = 0; i < 4; i++) c[j][i] = 0.f;

    // prologue: tile 0
    {
        float4 av  = loadA(0);
        float4 bv0 = loadB(0, 0);
        float4 bv1 = loadB(0, 1);
        storeTile(0, av, bv0, bv1);
    }
    __syncthreads();

    const int NIT = K / 32;
    for (int it = 0; it < NIT; it++) {
        int cb = it & 1, nb = cb ^ 1;
        float4 av, bv0, bv1;
        bool more = (it + 1 < NIT);
        if (more) {                       // issue next-tile LDGs early
            int k0 = (it + 1) * 32;
            av  = loadA(k0);
            bv0 = loadB(k0, 0);
            bv1 = loadB(k0, 1);
        }

#pragma unroll
        for (int ks = 0; ks < 4; ks++) {
            int kb = ks * 8;
            uint32_t a0 = __float_as_uint(As[cb][warp_m + group    ][kb + tig    ]);
            uint32_t a1 = __float_as_uint(As[cb][warp_m + group + 8][kb + tig    ]);
            uint32_t a2 = __float_as_uint(As[cb][warp_m + group    ][kb + tig + 4]);
            uint32_t a3 = __float_as_uint(As[cb][warp_m + group + 8][kb + tig + 4]);
#pragma unroll
            for (int j = 0; j < 2; j++) {
                int col = warp_n + j * 8 + group;
                uint32_t b0 = __float_as_uint(Bs[cb][kb + tig    ][col]);
                uint32_t b1 = __float_as_uint(Bs[cb][kb + tig + 4][col]);
                asm volatile(
                    "mma.sync.aligned.m16n8k8.row.col.f32.tf32.tf32.f32 "
                    "{%0,%1,%2,%3}, {%4,%5,%6,%7}, {%8,%9}, {%0,%1,%2,%3};"
                    : "+f"(c[j][0]), "+f"(c[j][1]), "+f"(c[j][2]), "+f"(c[j][3])
                    : "r"(a0), "r"(a1), "r"(a2), "r"(a3), "r"(b0), "r"(b1));
            }
        }

        if (more) storeTile(nb, av, bv0, bv1);
        __syncthreads();
    }

    // epilogue
#pragma unroll
    for (int j = 0; j < 2; j++) {
        int row = brow + warp_m + group;
        int col = bcol + warp_n + j * 8 + 2 * tig;
        float bc0 = bias[col], bc1 = bias[col + 1];
        float v00 = c[j][0] + bc0, v01 = c[j][1] + bc1;
        float v10 = c[j][2] + bc0, v11 = c[j][3] + bc1;
        if (FIRST) {
            v00 = fmaxf(v00, 0.f); v01 = fmaxf(v01, 0.f);
            v10 = fmaxf(v10, 0.f); v11 = fmaxf(v11, 0.f);
        }
        C[(size_t)row * N + col]           = v00;
        C[(size_t)row * N + col + 1]       = v01;
        C[(size_t)(row + 8) * N + col]     = v10;
        C[(size_t)(row + 8) * N + col + 1] = v11;
    }
}

// ---------------------------------------------------------------------------
// Scores: 8 threads/action, 32 actions/block, grid (8,B).
// Ent gathers batched into regs first (MLP=8/thread); rel streams (L2-hit).
// ---------------------------------------------------------------------------
__global__ void scores_kernel(const int* __restrict__ r_space,
                              const int* __restrict__ e_space,
                              const int* __restrict__ amask,
                              const float* __restrict__ rel_emb,
                              const float* __restrict__ ent_emb) {
    int b   = blockIdx.y;
    int tid = threadIdx.x;
    int al  = tid >> 3;
    int sub = tid & 7;
    int a   = blockIdx.x * 32 + al;

    __shared__ float x2s[ACT_DIM];
    x2s[tid]       = g_X2[(size_t)b * ACT_DIM + tid];
    x2s[tid + 256] = g_X2[(size_t)b * ACT_DIM + tid + 256];

    int r = r_space[b * NACT + a];
    int e = e_space[b * NACT + a];
    const float4* rp4 = reinterpret_cast<const float4*>(rel_emb + (size_t)r * REL_D);
    const float4* ep4 = reinterpret_cast<const float4*>(ent_emb + (size_t)e * ENT_D);

    // 1) issue all 8 ent gathers (DRAM-bound) as independent loads
    float4 ev[8];
#pragma unroll
    for (int i = 0; i < 8; i++) ev[i] = ep4[sub + i * 8];

    // 2) rel part (L2/L1-hit) while ent loads are in flight
    float4 rv[8];
#pragma unroll
    for (int i = 0; i < 8; i++) rv[i] = rp4[sub + i * 8];

    __syncthreads();
    const float4* xa = reinterpret_cast<const float4*>(x2s);

    float s = 0.f;
#pragma unroll
    for (int i = 0; i < 8; i++) {
        float4 xv = xa[sub + i * 8];
        s += rv[i].x * xv.x + rv[i].y * xv.y + rv[i].z * xv.z + rv[i].w * xv.w;
    }
#pragma unroll
    for (int i = 0; i < 8; i++) {
        float4 xw = xa[64 + sub + i * 8];
        s += ev[i].x * xw.x + ev[i].y * xw.y + ev[i].z * xw.z + ev[i].w * xw.w;
    }

    s += __shfl_xor_sync(0xffffffffu, s, 1);
    s += __shfl_xor_sync(0xffffffffu, s, 2);
    s += __shfl_xor_sync(0xffffffffu, s, 4);

    if (sub == 0) {
        float m = (float)amask[b * NACT + a];
        g_SC[b * NACT + a] = s - (1.0f - m) * HUGE_F;
    }
}

// ---------------------------------------------------------------------------
// Softmax + entropy per row.
// ---------------------------------------------------------------------------
__global__ void softmax_kernel(float* __restrict__ out) {
    int b    = blockIdx.x;
    int tid  = threadIdx.x;
    int lane = tid & 31;
    int warp = tid >> 5;
    __shared__ float red[8];

    float v = g_SC[b * NACT + tid];

    float m = v;
#pragma unroll
    for (int o = 16; o; o >>= 1) m = fmaxf(m, __shfl_xor_sync(0xffffffffu, m, o));
    if (lane == 0) red[warp] = m;
    __syncthreads();
    float mx = red[0];
#pragma unroll
    for (int i = 1; i < 8; i++) mx = fmaxf(mx, red[i]);
    __syncthreads();

    float ev = expf(v - mx);
    float s = ev;
#pragma unroll
    for (int o = 16; o; o >>= 1) s += __shfl_xor_sync(0xffffffffu, s, o);
    if (lane == 0) red[warp] = s;
    __syncthreads();
    float tot = red[0];
#pragma unroll
    for (int i = 1; i < 8; i++) tot += red[i];
    __syncthreads();

    float p = ev / tot;
    out[(size_t)b * NACT + tid] = p;

    float et = -p * logf(p + EPS_F);
#pragma unroll
    for (int o = 16; o; o >>= 1) et += __shfl_xor_sync(0xffffffffu, et, o);
    if (lane == 0) red[warp] = et;
    __syncthreads();
    if (tid == 0) {
        float e = red[0];
#pragma unroll
        for (int i = 1; i < 8; i++) e += red[i];
        out[(size_t)BATCH * NACT + b] = e;
    }
}

// ---------------------------------------------------------------------------
extern "C" void kernel_launch(void* const* d_in, const int* in_sizes, int n_in,
                              void* d_out, int out_size) {
    const int*   cur     = (const int*)  d_in[0];
    const int*   qr      = (const int*)  d_in[1];
    const float* hist    = (const float*)d_in[2];
    const int*   r_space = (const int*)  d_in[3];
    const int*   e_space = (const int*)  d_in[4];
    const int*   amask   = (const int*)  d_in[5];
    const float* ent_emb = (const float*)d_in[6];
    const float* rel_emb = (const float*)d_in[7];
    const float* W1      = (const float*)d_in[8];
    const float* b1      = (const float*)d_in[9];
    const float* W2      = (const float*)d_in[10];
    const float* b2      = (const float*)d_in[11];
    float* out = (float*)d_out;

    dim3 ggrid(ACT_DIM / 64, BATCH / 32);    // 8 x 16 = 128 blocks
    mma_gemm_kernel<IN_DIM,  true ><<<ggrid, 256>>>(W1, b1, cur, qr, hist, ent_emb, rel_emb);
    mma_gemm_kernel<ACT_DIM, false><<<ggrid, 256>>>(W2, b2, cur, qr, hist, ent_emb, rel_emb);

    dim3 sgrid(NACT / 32, BATCH);            // 8 x 512 = 4096 blocks
    scores_kernel<<<sgrid, 256>>>(r_space, e_space, amask, rel_emb, ent_emb);

    softmax_kernel<<<BATCH, 256>>>(out);
}